// round 1
// baseline (speedup 1.0000x reference)
#include <cuda_runtime.h>
#include <cuda_bf16.h>
#include <cstdint>

// ---------------------------------------------------------------------------
// BilateralRotation: out[b,c] = R1[c] @ wkv[b,c] @ R2[c]
//   R = Cayley(p) = (I - A)(I + A)^{-1},  A = 0.5 (p - p^T)
// Shapes: wkv [512,32,64,64] f32, p_left/p_right [32,64,64] f32.
// Stage 1: cayley_kernel  — 64 blocks, Gauss-Jordan inversion in SMEM.
// Stage 2: bilat_kernel   — 16384 blocks, tf32 mma.sync m16n8k8 double GEMM.
// ---------------------------------------------------------------------------

#define NUM_HEADS 32
#define DIM 64
#define SPAD 72            // SMEM row pitch (floats): conflict-free B-frag loads

// Scratch for the per-head rotation matrices (allocation-free rule).
__device__ float g_R1[NUM_HEADS * DIM * DIM];
__device__ float g_R2[NUM_HEADS * DIM * DIM];

__device__ __forceinline__ float tf32r(float x) {
    uint32_t u;
    asm("cvt.rna.tf32.f32 %0, %1;" : "=r"(u) : "f"(x));
    return __uint_as_float(u);
}

// ---------------------------------------------------------------------------
// Stage 1: Cayley transform. One block per (side, head).
// Gauss-Jordan with partial pivoting: X = (I+A)^{-1}; then R = (I-A) X.
// ---------------------------------------------------------------------------
__global__ __launch_bounds__(256) void cayley_kernel(
    const float* __restrict__ pL, const float* __restrict__ pR)
{
    const int side = blockIdx.x >> 5;        // 0 = left, 1 = right
    const int h    = blockIdx.x & 31;
    const float* p = (side ? pR : pL) + h * DIM * DIM;
    float* Rout    = (side ? g_R2 : g_R1) + h * DIM * DIM;

    __shared__ float M[DIM][66];   // I + A, becomes A at the end
    __shared__ float X[DIM][66];   // I, becomes (I+A)^{-1}
    __shared__ float fcol[DIM];
    __shared__ int   s_piv;
    __shared__ float s_inv;

    const int tid = threadIdx.x;

    // init M = I + A,  X = I
    for (int i = tid; i < DIM * DIM; i += 256) {
        int r = i >> 6, c = i & 63;
        float a = 0.5f * (p[r * DIM + c] - p[c * DIM + r]);
        M[r][c] = a + (r == c ? 1.0f : 0.0f);
        X[r][c] = (r == c) ? 1.0f : 0.0f;
    }
    __syncthreads();

    for (int k = 0; k < DIM; k++) {
        // --- pivot search (warp 0) ---
        if (tid < 32) {
            float best = -1.0f, bv = 1.0f;
            int bi = k;
            for (int i = k + tid; i < DIM; i += 32) {
                float v = M[i][k], av = fabsf(v);
                if (av > best) { best = av; bv = v; bi = i; }
            }
            for (int off = 16; off; off >>= 1) {
                float ob  = __shfl_down_sync(0xffffffffu, best, off);
                float obv = __shfl_down_sync(0xffffffffu, bv,   off);
                int   obi = __shfl_down_sync(0xffffffffu, bi,   off);
                if (ob > best) { best = ob; bv = obv; bi = obi; }
            }
            if (tid == 0) { s_piv = bi; s_inv = 1.0f / bv; }
        }
        __syncthreads();
        const int piv = s_piv;
        const float invp = s_inv;

        // --- row swap ---
        if (piv != k) {
            for (int c = tid; c < 2 * DIM; c += 256) {
                if (c < DIM) { float t = M[k][c]; M[k][c] = M[piv][c]; M[piv][c] = t; }
                else { int j = c - DIM; float t = X[k][j]; X[k][j] = X[piv][j]; X[piv][j] = t; }
            }
        }
        __syncthreads();

        // --- capture elimination factors + normalize pivot row ---
        if (tid < DIM) fcol[tid] = (tid == k) ? 0.0f : M[tid][k];
        for (int c = tid; c < 2 * DIM; c += 256) {
            if (c < DIM) M[k][c] *= invp; else X[k][c - DIM] *= invp;
        }
        __syncthreads();

        // --- eliminate all other rows ---
        for (int idx = tid; idx < DIM * 2 * DIM; idx += 256) {
            int r = idx >> 7, c = idx & 127;
            if (r == k) continue;
            float f = fcol[r];
            if (c < DIM) M[r][c] -= f * M[k][c];
            else { int j = c - DIM; X[r][j] -= f * X[k][j]; }
        }
        __syncthreads();
    }

    // rebuild A into M (M is now ~I, free to reuse)
    for (int i = tid; i < DIM * DIM; i += 256) {
        int r = i >> 6, c = i & 63;
        M[r][c] = 0.5f * (p[r * DIM + c] - p[c * DIM + r]);
    }
    __syncthreads();

    // R = X - A @ X
    for (int i = tid; i < DIM * DIM; i += 256) {
        int r = i >> 6, j = i & 63;
        float s = X[r][j];
        #pragma unroll 8
        for (int kk = 0; kk < DIM; kk++)
            s -= M[r][kk] * X[kk][j];
        Rout[r * DIM + j] = s;
    }
}

// ---------------------------------------------------------------------------
// Stage 2: bilateral rotation via two back-to-back tf32 MMA GEMMs.
// One block per (b,c), 128 threads (4 warps), each warp owns 16 output rows.
// ---------------------------------------------------------------------------
__device__ __forceinline__ void gemm64_tf32(
    const float* __restrict__ Am, const float* __restrict__ Bm,
    float acc[8][4], int row0, int tig, int grp)
{
    #pragma unroll
    for (int kb = 0; kb < 64; kb += 8) {
        uint32_t a0 = __float_as_uint(Am[ row0      * SPAD + kb + tig]);
        uint32_t a1 = __float_as_uint(Am[(row0 + 8) * SPAD + kb + tig]);
        uint32_t a2 = __float_as_uint(Am[ row0      * SPAD + kb + tig + 4]);
        uint32_t a3 = __float_as_uint(Am[(row0 + 8) * SPAD + kb + tig + 4]);
        #pragma unroll
        for (int nt = 0; nt < 8; nt++) {
            uint32_t b0 = __float_as_uint(Bm[(kb + tig)     * SPAD + nt * 8 + grp]);
            uint32_t b1 = __float_as_uint(Bm[(kb + tig + 4) * SPAD + nt * 8 + grp]);
            asm volatile(
                "mma.sync.aligned.m16n8k8.row.col.f32.tf32.tf32.f32 "
                "{%0,%1,%2,%3}, {%4,%5,%6,%7}, {%8,%9}, {%0,%1,%2,%3};\n"
                : "+f"(acc[nt][0]), "+f"(acc[nt][1]), "+f"(acc[nt][2]), "+f"(acc[nt][3])
                : "r"(a0), "r"(a1), "r"(a2), "r"(a3), "r"(b0), "r"(b1));
        }
    }
}

__global__ __launch_bounds__(128) void bilat_kernel(
    const float* __restrict__ wkv, float* __restrict__ out)
{
    const int bc = blockIdx.x;          // b-major, c-minor: offset = bc*4096
    const int c  = bc & (NUM_HEADS - 1);

    __shared__ float sA[DIM * SPAD];    // W, then T
    __shared__ float sB[DIM * SPAD];    // R2, then R1

    const int tid  = threadIdx.x;
    const int lane = tid & 31;
    const int warp = tid >> 5;
    const int grp  = lane >> 2;         // 0..7
    const int tig  = lane & 3;          // 0..3
    const int row0 = warp * 16 + grp;

    // --- stage W (A) and R2 (B), rounding to tf32 ---
    const float4* wsrc  = reinterpret_cast<const float4*>(wkv)  + (size_t)bc * 1024;
    const float4* r2src = reinterpret_cast<const float4*>(g_R2) + (size_t)c  * 1024;
    #pragma unroll
    for (int i = tid; i < 1024; i += 128) {
        int r = i >> 4, c4 = (i & 15) << 2;
        float4 v = wsrc[i];
        float* d = &sA[r * SPAD + c4];
        d[0] = tf32r(v.x); d[1] = tf32r(v.y); d[2] = tf32r(v.z); d[3] = tf32r(v.w);
        float4 u = r2src[i];
        float* e = &sB[r * SPAD + c4];
        e[0] = tf32r(u.x); e[1] = tf32r(u.y); e[2] = tf32r(u.z); e[3] = tf32r(u.w);
    }
    __syncthreads();

    float acc[8][4];
    #pragma unroll
    for (int nt = 0; nt < 8; nt++)
        { acc[nt][0] = 0.f; acc[nt][1] = 0.f; acc[nt][2] = 0.f; acc[nt][3] = 0.f; }

    // --- GEMM1: T = W @ R2 ---
    gemm64_tf32(sA, sB, acc, row0, tig, grp);
    __syncthreads();   // all warps done reading sA/sB

    // --- T -> sA (tf32-rounded), R1 -> sB ---
    #pragma unroll
    for (int nt = 0; nt < 8; nt++) {
        int col = nt * 8 + 2 * tig;
        sA[ row0      * SPAD + col    ] = tf32r(acc[nt][0]);
        sA[ row0      * SPAD + col + 1] = tf32r(acc[nt][1]);
        sA[(row0 + 8) * SPAD + col    ] = tf32r(acc[nt][2]);
        sA[(row0 + 8) * SPAD + col + 1] = tf32r(acc[nt][3]);
    }
    const float4* r1src = reinterpret_cast<const float4*>(g_R1) + (size_t)c * 1024;
    #pragma unroll
    for (int i = tid; i < 1024; i += 128) {
        int r = i >> 4, c4 = (i & 15) << 2;
        float4 u = r1src[i];
        float* e = &sB[r * SPAD + c4];
        e[0] = tf32r(u.x); e[1] = tf32r(u.y); e[2] = tf32r(u.z); e[3] = tf32r(u.w);
    }
    #pragma unroll
    for (int nt = 0; nt < 8; nt++)
        { acc[nt][0] = 0.f; acc[nt][1] = 0.f; acc[nt][2] = 0.f; acc[nt][3] = 0.f; }
    __syncthreads();

    // --- GEMM2: out = R1 @ T ---
    gemm64_tf32(sB, sA, acc, row0, tig, grp);

    // --- epilogue: coalesced float2 stores ---
    float* dst = out + (size_t)bc * (DIM * DIM);
    #pragma unroll
    for (int nt = 0; nt < 8; nt++) {
        int col = nt * 8 + 2 * tig;
        *reinterpret_cast<float2*>(dst +  row0      * DIM + col) =
            make_float2(acc[nt][0], acc[nt][1]);
        *reinterpret_cast<float2*>(dst + (row0 + 8) * DIM + col) =
            make_float2(acc[nt][2], acc[nt][3]);
    }
}

// ---------------------------------------------------------------------------
extern "C" void kernel_launch(void* const* d_in, const int* in_sizes, int n_in,
                              void* d_out, int out_size)
{
    const float* wkv = (const float*)d_in[0];
    const float* pL  = (const float*)d_in[1];
    const float* pR  = (const float*)d_in[2];
    float* out       = (float*)d_out;

    cayley_kernel<<<2 * NUM_HEADS, 256>>>(pL, pR);
    bilat_kernel<<<512 * NUM_HEADS, 128>>>(wkv, out);
}

// round 3
// speedup vs baseline: 1.7148x; 1.7148x over previous
#include <cuda_runtime.h>
#include <cuda_bf16.h>
#include <cstdint>

// ---------------------------------------------------------------------------
// BilateralRotation: out[b,c] = R1[c] @ wkv[b,c] @ R2[c]
//   R = Cayley(p) = (I - A)(I + A)^{-1},  A = 0.5 (p - p^T)
//
// Stage 1: cayley_kernel — register-resident unpivoted Gauss-Jordan.
//          Emits g_R1 row-major [r][c] and g_R2T transposed [c][r].
// Stage 2: bilat_kernel — 4096 blocks (head-major), 4 warps, 32x64 warp
//          tiles, 4 batches/block sharing one R staging, tf32 mma.sync.
// ---------------------------------------------------------------------------

#define NUM_HEADS 32
#define DIM 64
#define PITCH 68           // pitch mod 32 == 4 -> bank = 4*grp + tig (unique)

__device__ float g_R1 [NUM_HEADS * DIM * DIM];   // R1 row-major
__device__ float g_R2T[NUM_HEADS * DIM * DIM];   // R2 transposed [n][k]

__device__ __forceinline__ float tf32r(float x) {
    uint32_t u;
    asm("cvt.rna.tf32.f32 %0, %1;" : "=r"(u) : "f"(x));
    return __uint_as_float(u);
}

// ---------------------------------------------------------------------------
// Stage 1: Cayley. One block per (side, head), 256 threads.
// Thread (r = tid>>2, q = tid&3) owns cols [q*16, q*16+16) of row r of
// M = I + A and X (register resident). Unpivoted GJ: symmetric part of I+A
// is SPD, so diagonal pivots stay positive -> no pivoting needed.
// ---------------------------------------------------------------------------
__global__ __launch_bounds__(256) void cayley_kernel(
    const float* __restrict__ pL, const float* __restrict__ pR)
{
    const int side = blockIdx.x >> 5;
    const int h    = blockIdx.x & 31;
    const float* p = (side ? pR : pL) + h * DIM * DIM;

    const int tid = threadIdx.x;
    const int r   = tid >> 2;
    const int q   = tid & 3;
    const int cb  = q * 16;

    __shared__ float rowM[DIM], rowX[DIM], colM[DIM];
    __shared__ float sX[DIM][PITCH];

    float m[16], x[16];
    #pragma unroll
    for (int j = 0; j < 16; j++) {
        int c = cb + j;
        float a = 0.5f * (p[r * DIM + c] - p[c * DIM + r]);
        m[j] = a + (r == c ? 1.0f : 0.0f);
        x[j] = (r == c) ? 1.0f : 0.0f;
    }
    __syncthreads();

    #pragma unroll 1
    for (int k = 0; k < DIM; k++) {
        if (r == k) {
            #pragma unroll
            for (int j = 0; j < 16; j++) { rowM[cb + j] = m[j]; rowX[cb + j] = x[j]; }
        }
        if ((k >> 4) == q) colM[r] = m[k & 15];
        __syncthreads();

        const float invp = 1.0f / rowM[k];
        if (r == k) {
            #pragma unroll
            for (int j = 0; j < 16; j++) { m[j] *= invp; x[j] *= invp; }
        } else {
            const float f = colM[r] * invp;
            #pragma unroll
            for (int j = 0; j < 16; j++) {
                m[j] -= f * rowM[cb + j];
                x[j] -= f * rowX[cb + j];
            }
        }
        __syncthreads();
    }

    // X = (I+A)^{-1} now lives in x[]; spill to SMEM for the final matmul.
    #pragma unroll
    for (int j = 0; j < 16; j++) sX[r][cb + j] = x[j];
    __syncthreads();

    // R[r][:] = X[r][:] - sum_l A[r][l] * X[l][:]
    float acc[16];
    #pragma unroll
    for (int j = 0; j < 16; j++) acc[j] = x[j];
    #pragma unroll 8
    for (int l = 0; l < DIM; l++) {
        float a_rl = 0.5f * (p[r * DIM + l] - p[l * DIM + r]);
        #pragma unroll
        for (int j = 0; j < 16; j++) acc[j] -= a_rl * sX[l][cb + j];
    }

    if (side == 0) {
        float* dst = g_R1 + h * DIM * DIM;
        #pragma unroll
        for (int j = 0; j < 16; j++) dst[r * DIM + cb + j] = acc[j];
    } else {
        float* dst = g_R2T + h * DIM * DIM;
        #pragma unroll
        for (int j = 0; j < 16; j++) dst[(cb + j) * DIM + r] = acc[j];
    }
}

// ---------------------------------------------------------------------------
// Stage 2: bilateral rotation. 128 threads = 2 warp-pairs; each pair owns one
// batch per pass (2 passes -> 4 batches/block, all same head).
// Warp tile 32x64: B fragments reused across two 16-row m-tiles.
// ---------------------------------------------------------------------------
#define SMEM_MAT (DIM * PITCH)       // 4352 floats = 17408 B
#define SMEM_TOTAL_BYTES (4 * SMEM_MAT * 4)   // R1, R2T, W0, W1 = 69632 B

__device__ __forceinline__ void gemm32x64_tf32(
    const float* __restrict__ Am,   // A [m][k], pitch PITCH; rows base..base+31
    const float* __restrict__ Bm,   // B stored [n][k], pitch PITCH
    float acc[2][8][4], int base, int grp, int tig)
{
    #pragma unroll
    for (int kb = 0; kb < DIM; kb += 8) {
        uint32_t a[2][4];
        #pragma unroll
        for (int mt = 0; mt < 2; mt++) {
            int r0 = base + mt * 16 + grp;
            a[mt][0] = __float_as_uint(Am[ r0      * PITCH + kb + tig    ]);
            a[mt][1] = __float_as_uint(Am[(r0 + 8) * PITCH + kb + tig    ]);
            a[mt][2] = __float_as_uint(Am[ r0      * PITCH + kb + tig + 4]);
            a[mt][3] = __float_as_uint(Am[(r0 + 8) * PITCH + kb + tig + 4]);
        }
        #pragma unroll
        for (int nt = 0; nt < 8; nt++) {
            uint32_t b0 = __float_as_uint(Bm[(nt * 8 + grp) * PITCH + kb + tig    ]);
            uint32_t b1 = __float_as_uint(Bm[(nt * 8 + grp) * PITCH + kb + tig + 4]);
            #pragma unroll
            for (int mt = 0; mt < 2; mt++) {
                asm volatile(
                    "mma.sync.aligned.m16n8k8.row.col.f32.tf32.tf32.f32 "
                    "{%0,%1,%2,%3}, {%4,%5,%6,%7}, {%8,%9}, {%0,%1,%2,%3};\n"
                    : "+f"(acc[mt][nt][0]), "+f"(acc[mt][nt][1]),
                      "+f"(acc[mt][nt][2]), "+f"(acc[mt][nt][3])
                    : "r"(a[mt][0]), "r"(a[mt][1]), "r"(a[mt][2]), "r"(a[mt][3]),
                      "r"(b0), "r"(b1));
            }
        }
    }
}

__global__ __launch_bounds__(128) void bilat_kernel(
    const float* __restrict__ wkv, float* __restrict__ out)
{
    extern __shared__ float smem[];
    float* sR1  = smem;                 // A operand of GEMM2
    float* sR2T = smem + SMEM_MAT;      // B operand of GEMM1
    float* sWp[2] = { smem + 2 * SMEM_MAT, smem + 3 * SMEM_MAT };

    const int blk  = blockIdx.x;
    const int head = blk >> 7;          // head-major: L2-hot R matrices
    const int g    = blk & 127;

    const int tid    = threadIdx.x;
    const int lane   = tid & 31;
    const int warp   = tid >> 5;
    const int pairid = warp >> 1;       // 0,1: which batch in this pass
    const int w2     = warp & 1;        // row half within the batch
    const int grp    = lane >> 2;
    const int tig    = lane & 3;
    const int base   = w2 * 32;

    // ---- stage R1 (row-major) and R2T ([n][k]) once, tf32-rounded ----
    {
        const float4* r1 = reinterpret_cast<const float4*>(g_R1)  + (size_t)head * 1024;
        const float4* r2 = reinterpret_cast<const float4*>(g_R2T) + (size_t)head * 1024;
        #pragma unroll
        for (int i = tid; i < 1024; i += 128) {
            int rr = i >> 4, c4 = (i & 15) << 2;
            float4 v = r1[i];
            float* d = &sR1[rr * PITCH + c4];
            d[0] = tf32r(v.x); d[1] = tf32r(v.y); d[2] = tf32r(v.z); d[3] = tf32r(v.w);
            float4 u = r2[i];
            float* e = &sR2T[rr * PITCH + c4];
            e[0] = tf32r(u.x); e[1] = tf32r(u.y); e[2] = tf32r(u.z); e[3] = tf32r(u.w);
        }
    }

    #pragma unroll 1
    for (int pass = 0; pass < 2; pass++) {
        const int b = g * 4 + pass * 2 + pairid;
        float* sW = sWp[pairid];

        if (pass) __syncthreads();      // prior pass done reading sW

        // ---- each 64-thread pair stages its own W (tf32-rounded) ----
        {
            const float4* wsrc = reinterpret_cast<const float4*>(wkv)
                               + (size_t)(b * NUM_HEADS + head) * 1024;
            const int tp = (tid & 63);
            #pragma unroll
            for (int i = tp; i < 1024; i += 64) {
                int rr = i >> 4, c4 = (i & 15) << 2;
                float4 v = wsrc[i];
                float* d = &sW[rr * PITCH + c4];
                d[0] = tf32r(v.x); d[1] = tf32r(v.y); d[2] = tf32r(v.z); d[3] = tf32r(v.w);
            }
        }
        __syncthreads();

        // ---- GEMM1: T = W @ R2  (A = sW, B = sR2T) ----
        float acc[2][8][4];
        #pragma unroll
        for (int mt = 0; mt < 2; mt++)
            #pragma unroll
            for (int nt = 0; nt < 8; nt++)
                { acc[mt][nt][0]=0.f; acc[mt][nt][1]=0.f; acc[mt][nt][2]=0.f; acc[mt][nt][3]=0.f; }

        gemm32x64_tf32(sW, sR2T, acc, base, grp, tig);
        __syncthreads();                // pair done reading sW

        // ---- write T transposed [j][l] into sW (tf32-rounded) ----
        #pragma unroll
        for (int mt = 0; mt < 2; mt++) {
            int r0 = base + mt * 16 + grp;
            #pragma unroll
            for (int nt = 0; nt < 8; nt++) {
                int col = nt * 8 + 2 * tig;
                sW[ col      * PITCH + r0    ] = tf32r(acc[mt][nt][0]);
                sW[(col + 1) * PITCH + r0    ] = tf32r(acc[mt][nt][1]);
                sW[ col      * PITCH + r0 + 8] = tf32r(acc[mt][nt][2]);
                sW[(col + 1) * PITCH + r0 + 8] = tf32r(acc[mt][nt][3]);
            }
        }
        __syncthreads();

        // ---- GEMM2: out = R1 @ T  (A = sR1, B = sW as T^T [j][l]) ----
        #pragma unroll
        for (int mt = 0; mt < 2; mt++)
            #pragma unroll
            for (int nt = 0; nt < 8; nt++)
                { acc[mt][nt][0]=0.f; acc[mt][nt][1]=0.f; acc[mt][nt][2]=0.f; acc[mt][nt][3]=0.f; }

        gemm32x64_tf32(sR1, sW, acc, base, grp, tig);

        // ---- epilogue: coalesced float2 stores ----
        float* dst = out + (size_t)(b * NUM_HEADS + head) * (DIM * DIM);
        #pragma unroll
        for (int mt = 0; mt < 2; mt++) {
            int r0 = base + mt * 16 + grp;
            #pragma unroll
            for (int nt = 0; nt < 8; nt++) {
                int col = nt * 8 + 2 * tig;
                *reinterpret_cast<float2*>(dst +  r0      * DIM + col) =
                    make_float2(acc[mt][nt][0], acc[mt][nt][1]);
                *reinterpret_cast<float2*>(dst + (r0 + 8) * DIM + col) =
                    make_float2(acc[mt][nt][2], acc[mt][nt][3]);
            }
        }
    }
}

// ---------------------------------------------------------------------------
extern "C" void kernel_launch(void* const* d_in, const int* in_sizes, int n_in,
                              void* d_out, int out_size)
{
    const float* wkv = (const float*)d_in[0];
    const float* pL  = (const float*)d_in[1];
    const float* pR  = (const float*)d_in[2];
    float* out       = (float*)d_out;

    // Unconditional (no static guard — determinism rule). Not a stream op,
    // executes immediately, idempotent; safe under graph capture.
    cudaFuncSetAttribute(bilat_kernel,
                         cudaFuncAttributeMaxDynamicSharedMemorySize,
                         SMEM_TOTAL_BYTES);

    cayley_kernel<<<2 * NUM_HEADS, 256>>>(pL, pR);
    bilat_kernel<<<NUM_HEADS * 128, 128, SMEM_TOTAL_BYTES>>>(wkv, out);
}

// round 5
// speedup vs baseline: 2.0423x; 1.1910x over previous
#include <cuda_runtime.h>
#include <cuda_bf16.h>
#include <cstdint>

// ---------------------------------------------------------------------------
// BilateralRotation: out[b,c] = R1[c] @ wkv[b,c] @ R2[c]
//   R = Cayley(p) = (I - A)(I + A)^{-1},  A = 0.5 (p - p^T)
//
// Stage 1: cayley_kernel — register-resident unpivoted Gauss-Jordan.
// Stage 2: bilat_kernel — 4096 blocks, 128 thr, XOR-swizzled pitch-64 SMEM
//          (4 x 16KB -> 3 CTAs/SM), cp.async staging, tf32 mma.sync.
// ---------------------------------------------------------------------------

#define NUM_HEADS 32
#define DIM 64
#define MATF 4096                       // floats per 64x64 buffer (16 KB)
#define SMEM_TOTAL_BYTES (4 * MATF * 4) // sR1, sR2T, sW0, sW1 = 65536 B

__device__ float g_R1 [NUM_HEADS * DIM * DIM];   // R1 row-major
__device__ float g_R2T[NUM_HEADS * DIM * DIM];   // R2 transposed [n][k]

__device__ __forceinline__ float tf32r(float x) {
    uint32_t u;
    asm("cvt.rna.tf32.f32 %0, %1;" : "=r"(u) : "f"(x));
    return __uint_as_float(u);
}

__device__ __forceinline__ void cp16(float* dst_smem, const void* src) {
    uint32_t d = (uint32_t)__cvta_generic_to_shared(dst_smem);
    asm volatile("cp.async.ca.shared.global [%0], [%1], 16;\n" :: "r"(d), "l"(src));
}
#define CP_COMMIT() asm volatile("cp.async.commit_group;\n")
#define CP_WAIT0()  asm volatile("cp.async.wait_group 0;\n" ::: "memory")
#define CP_WAIT1()  asm volatile("cp.async.wait_group 1;\n" ::: "memory")

__device__ __forceinline__ void pbar(int id) {
    asm volatile("bar.sync %0, 64;" :: "r"(id) : "memory");
}

// ---------------------------------------------------------------------------
// Stage 1: Cayley. One block per (side, head), 256 threads.
// Thread (r = tid>>2, q = tid&3) owns 16 cols of row r, register resident.
// Unpivoted GJ: symmetric part of I+A is SPD -> diagonal pivots are safe.
// ---------------------------------------------------------------------------
__global__ __launch_bounds__(256) void cayley_kernel(
    const float* __restrict__ pL, const float* __restrict__ pR)
{
    const int side = blockIdx.x >> 5;
    const int h    = blockIdx.x & 31;
    const float* p = (side ? pR : pL) + h * DIM * DIM;

    const int tid = threadIdx.x;
    const int r   = tid >> 2;
    const int q   = tid & 3;
    const int cb  = q * 16;

    __shared__ float rowM[DIM], rowX[DIM], colM[DIM];
    __shared__ float sX[DIM][DIM + 4];

    float m[16], x[16];
    #pragma unroll
    for (int j = 0; j < 16; j++) {
        int c = cb + j;
        float a = 0.5f * (p[r * DIM + c] - p[c * DIM + r]);
        m[j] = a + (r == c ? 1.0f : 0.0f);
        x[j] = (r == c) ? 1.0f : 0.0f;
    }
    __syncthreads();

    #pragma unroll 1
    for (int k = 0; k < DIM; k++) {
        if (r == k) {
            #pragma unroll
            for (int j = 0; j < 16; j++) { rowM[cb + j] = m[j]; rowX[cb + j] = x[j]; }
        }
        if ((k >> 4) == q) colM[r] = m[k & 15];
        __syncthreads();

        const float invp = 1.0f / rowM[k];
        if (r == k) {
            #pragma unroll
            for (int j = 0; j < 16; j++) { m[j] *= invp; x[j] *= invp; }
        } else {
            const float f = colM[r] * invp;
            #pragma unroll
            for (int j = 0; j < 16; j++) {
                m[j] -= f * rowM[cb + j];
                x[j] -= f * rowX[cb + j];
            }
        }
        __syncthreads();
    }

    #pragma unroll
    for (int j = 0; j < 16; j++) sX[r][cb + j] = x[j];
    __syncthreads();

    // R[r][:] = X[r][:] - sum_l A[r][l] * X[l][:]
    float acc[16];
    #pragma unroll
    for (int j = 0; j < 16; j++) acc[j] = x[j];
    #pragma unroll 8
    for (int l = 0; l < DIM; l++) {
        float a_rl = 0.5f * (p[r * DIM + l] - p[l * DIM + r]);
        #pragma unroll
        for (int j = 0; j < 16; j++) acc[j] -= a_rl * sX[l][cb + j];
    }

    if (side == 0) {
        float* dst = g_R1 + h * DIM * DIM;
        #pragma unroll
        for (int j = 0; j < 16; j++) dst[r * DIM + cb + j] = acc[j];
    } else {
        float* dst = g_R2T + h * DIM * DIM;
        #pragma unroll
        for (int j = 0; j < 16; j++) dst[(cb + j) * DIM + r] = acc[j];
    }
}

// ---------------------------------------------------------------------------
// Stage 2: bilateral rotation.
// SMEM layout: pitch 64 with XOR swizzle  col' = col ^ (4*(row&7)).
// Conflict-free for 32-bit frag loads (bank = f(grp,tig) distinct), for the
// T^T scatter stores, and compatible with 16B cp.async chunks.
// ---------------------------------------------------------------------------
template<bool CVTA>
__device__ __forceinline__ void gemm32x64(
    const float* __restrict__ Am,   // A [m][k] swizzled; rows base..base+31
    const float* __restrict__ Bm,   // B [n][k] swizzled
    float acc[2][8][4], int base, int grp, int tig)
{
    #pragma unroll
    for (int kb = 0; kb < DIM; kb += 8) {
        const int cx0 = (kb + tig)     ^ (grp << 2);
        const int cx4 = (kb + tig + 4) ^ (grp << 2);
        uint32_t a[2][4];
        #pragma unroll
        for (int mt = 0; mt < 2; mt++) {
            const int r0 = base + mt * 16 + grp;
            float a0 = Am[ r0      * DIM + cx0];
            float a1 = Am[(r0 + 8) * DIM + cx0];
            float a2 = Am[ r0      * DIM + cx4];
            float a3 = Am[(r0 + 8) * DIM + cx4];
            if (CVTA) { a0 = tf32r(a0); a1 = tf32r(a1); a2 = tf32r(a2); a3 = tf32r(a3); }
            a[mt][0] = __float_as_uint(a0); a[mt][1] = __float_as_uint(a1);
            a[mt][2] = __float_as_uint(a2); a[mt][3] = __float_as_uint(a3);
        }
        #pragma unroll
        for (int nt = 0; nt < 8; nt++) {
            const int n = nt * 8 + grp;
            uint32_t b0 = __float_as_uint(Bm[n * DIM + cx0]);
            uint32_t b1 = __float_as_uint(Bm[n * DIM + cx4]);
            #pragma unroll
            for (int mt = 0; mt < 2; mt++) {
                asm volatile(
                    "mma.sync.aligned.m16n8k8.row.col.f32.tf32.tf32.f32 "
                    "{%0,%1,%2,%3}, {%4,%5,%6,%7}, {%8,%9}, {%0,%1,%2,%3};\n"
                    : "+f"(acc[mt][nt][0]), "+f"(acc[mt][nt][1]),
                      "+f"(acc[mt][nt][2]), "+f"(acc[mt][nt][3])
                    : "r"(a[mt][0]), "r"(a[mt][1]), "r"(a[mt][2]), "r"(a[mt][3]),
                      "r"(b0), "r"(b1));
            }
        }
    }
}

__global__ __launch_bounds__(128, 3) void bilat_kernel(
    const float* __restrict__ wkv, float* __restrict__ out)
{
    extern __shared__ float smem[];
    float* sR1  = smem;                  // A of GEMM2 (pre-rounded)
    float* sR2T = smem + MATF;           // B of GEMM1 (pre-rounded)

    const int blk  = blockIdx.x;
    const int head = blk >> 7;           // head-major: R matrices L2-hot
    const int g    = blk & 127;

    const int tid    = threadIdx.x;
    const int lane   = tid & 31;
    const int warp   = tid >> 5;
    const int pairid = warp >> 1;        // 0,1
    const int w2     = warp & 1;
    const int grp    = lane >> 2;
    const int tig    = lane & 3;
    const int base   = w2 * 32;
    const int tp     = tid & 63;

    float* sW = smem + 2 * MATF + pairid * MATF;

    // ---- cp.async: R1 + R2T (raw), group c0 ----
    {
        const float4* r1g = reinterpret_cast<const float4*>(g_R1)  + (size_t)head * 1024;
        const float4* r2g = reinterpret_cast<const float4*>(g_R2T) + (size_t)head * 1024;
        #pragma unroll 4
        for (int ci = tid; ci < 1024; ci += 128) {
            int r = ci >> 4, c = (ci & 15) << 2;
            int cx = c ^ ((r & 7) << 2);
            cp16(&sR1 [r * DIM + cx], r1g + ci);
            cp16(&sR2T[r * DIM + cx], r2g + ci);
        }
    }
    CP_COMMIT();   // c0

    // ---- cp.async: W for pass 0 (raw), group c1 ----
    {
        const int b0 = g * 4 + pairid;
        const float4* wsrc = reinterpret_cast<const float4*>(wkv)
                           + (size_t)(b0 * NUM_HEADS + head) * 1024;
        #pragma unroll 4
        for (int ci = tp; ci < 1024; ci += 64) {
            int r = ci >> 4, c = (ci & 15) << 2;
            int cx = c ^ ((r & 7) << 2);
            cp16(&sW[r * DIM + cx], wsrc + ci);
        }
    }
    CP_COMMIT();   // c1

    // ---- R arrived: in-place tf32 rounding of sR1+sR2T (linear sweep) ----
    CP_WAIT1();
    __syncthreads();
    {
        float4* rp = reinterpret_cast<float4*>(smem);   // first 8192 floats
        #pragma unroll 4
        for (int i = tid; i < 2048; i += 128) {
            float4 v = rp[i];
            v.x = tf32r(v.x); v.y = tf32r(v.y); v.z = tf32r(v.z); v.w = tf32r(v.w);
            rp[i] = v;
        }
    }
    __syncthreads();

    #pragma unroll 1
    for (int pass = 0; pass < 2; pass++) {
        const int b = g * 4 + pass * 2 + pairid;

        CP_WAIT0();            // this pass's W chunks (own thread) done
        pbar(1 + pairid);      // all pair threads' chunks visible

        // ---- GEMM1: T = W @ R2   (A = raw W with inline cvt, B = sR2T) ----
        float acc[2][8][4];
        #pragma unroll
        for (int mt = 0; mt < 2; mt++)
            #pragma unroll
            for (int nt = 0; nt < 8; nt++)
                { acc[mt][nt][0]=0.f; acc[mt][nt][1]=0.f; acc[mt][nt][2]=0.f; acc[mt][nt][3]=0.f; }
        gemm32x64<true>(sW, sR2T, acc, base, grp, tig);
        pbar(1 + pairid);      // pair done reading W

        // ---- write T^T into sW (swizzled, tf32-rounded) ----
        #pragma unroll
        for (int mt = 0; mt < 2; mt++) {
            const int r0 = base + mt * 16 + grp;
            #pragma unroll
            for (int nt = 0; nt < 8; nt++) {
                const int c0 = nt * 8 + 2 * tig;
                const int c1 = c0 + 1;
                sW[c0 * DIM + ( r0      ^ ((c0 & 7) << 2))] = tf32r(acc[mt][nt][0]);
                sW[c1 * DIM + ( r0      ^ ((c1 & 7) << 2))] = tf32r(acc[mt][nt][1]);
                sW[c0 * DIM + ((r0 + 8) ^ ((c0 & 7) << 2))] = tf32r(acc[mt][nt][2]);
                sW[c1 * DIM + ((r0 + 8) ^ ((c1 & 7) << 2))] = tf32r(acc[mt][nt][3]);
            }
        }
        pbar(1 + pairid);

        // ---- GEMM2: out = R1 @ T   (A = sR1, B = T^T in sW) ----
        #pragma unroll
        for (int mt = 0; mt < 2; mt++)
            #pragma unroll
            for (int nt = 0; nt < 8; nt++)
                { acc[mt][nt][0]=0.f; acc[mt][nt][1]=0.f; acc[mt][nt][2]=0.f; acc[mt][nt][3]=0.f; }
        gemm32x64<false>(sR1, sW, acc, base, grp, tig);
        pbar(1 + pairid);      // sW free

        // ---- prefetch next pass's W (overlaps epilogue stores) ----
        if (pass == 0) {
            const int bn = g * 4 + 2 + pairid;
            const float4* wsrc = reinterpret_cast<const float4*>(wkv)
                               + (size_t)(bn * NUM_HEADS + head) * 1024;
            #pragma unroll 4
            for (int ci = tp; ci < 1024; ci += 64) {
                int r = ci >> 4, c = (ci & 15) << 2;
                int cx = c ^ ((r & 7) << 2);
                cp16(&sW[r * DIM + cx], wsrc + ci);
            }
            CP_COMMIT();       // c2
        }

        // ---- epilogue: coalesced float2 stores ----
        float* dst = out + (size_t)(b * NUM_HEADS + head) * (DIM * DIM);
        #pragma unroll
        for (int mt = 0; mt < 2; mt++) {
            const int r0 = base + mt * 16 + grp;
            #pragma unroll
            for (int nt = 0; nt < 8; nt++) {
                const int col = nt * 8 + 2 * tig;
                *reinterpret_cast<float2*>(dst +  r0      * DIM + col) =
                    make_float2(acc[mt][nt][0], acc[mt][nt][1]);
                *reinterpret_cast<float2*>(dst + (r0 + 8) * DIM + col) =
                    make_float2(acc[mt][nt][2], acc[mt][nt][3]);
            }
        }
    }
}

// ---------------------------------------------------------------------------
extern "C" void kernel_launch(void* const* d_in, const int* in_sizes, int n_in,
                              void* d_out, int out_size)
{
    const float* wkv = (const float*)d_in[0];
    const float* pL  = (const float*)d_in[1];
    const float* pR  = (const float*)d_in[2];
    float* out       = (float*)d_out;

    // Unconditional (no static guard). Immediate host-side API, idempotent,
    // safe under graph capture.
    cudaFuncSetAttribute(bilat_kernel,
                         cudaFuncAttributeMaxDynamicSharedMemorySize,
                         SMEM_TOTAL_BYTES);

    cayley_kernel<<<2 * NUM_HEADS, 256>>>(pL, pR);
    bilat_kernel<<<NUM_HEADS * 128, 128, SMEM_TOTAL_BYTES>>>(wkv, out);
}